// round 5
// baseline (speedup 1.0000x reference)
#include <cuda_runtime.h>
#include <cuda_fp16.h>
#include <cstdint>

#define N_MAX   1000000
#define DDIM    256
#define B_MAX   4096

__device__ float g_s[N_MAX];
__device__ float g_pooled[B_MAX * DDIM];

// ---------------- score kernel ----------------
// smem layout (bytes):
//   Wt  (half) 256 x 264   @ 0        (135168)
//   As  (half) 128 x 264   @ 135168   (67584)
//   b1s (float) 256        @ 202752   (1024)
//   w2s (float) 256        @ 203776   (1024)
//   red (float) 128        @ 204800   (512)
#define WT_STRIDE 264
#define SMEM_BYTES 205312

__device__ __forceinline__ float tanh_fast(float v) {
    // tanh(v) = 1 - 2/(1+exp(2v)); MUFU-based, ~1e-6 rel err
    float e = __expf(2.0f * v);
    return 1.0f - __fdividef(2.0f, 1.0f + e);
}

__global__ __launch_bounds__(512, 1)
void score_kernel(const float* __restrict__ x,
                  const float* __restrict__ W1,
                  const float* __restrict__ b1,
                  const float* __restrict__ w2,
                  const float* __restrict__ b2p,
                  float* __restrict__ s_out,
                  int N, int nTiles)
{
    extern __shared__ char smem[];
    __half* Wt  = (__half*)smem;
    __half* As  = (__half*)(smem + 135168);
    float*  b1s = (float*)(smem + 202752);
    float*  w2s = (float*)(smem + 203776);
    float*  red = (float*)(smem + 204800);

    const int tid  = threadIdx.x;
    const int lane = tid & 31;
    const int wid  = tid >> 5;
    const int mw   = wid >> 2;   // 0..3 (M warp row)
    const int nw   = wid & 3;    // 0..3 (N warp col)

    // Load W1 transposed into Wt[n][k] as fp16 (once per CTA).
    for (int p = tid; p < 256 * 128; p += 512) {
        int n  = p & 255;
        int k2 = p >> 8;   // pair of k values
        float f0 = W1[(2 * k2) * 256 + n];
        float f1 = W1[(2 * k2 + 1) * 256 + n];
        *(__half2*)&Wt[n * WT_STRIDE + 2 * k2] = __floats2half2_rn(f0, f1);
    }
    if (tid < 256) { b1s[tid] = b1[tid]; w2s[tid] = w2[tid]; }
    const float b2 = __ldg(b2p);
    __syncthreads();

    const uint32_t* As32 = (const uint32_t*)As;
    const uint32_t* Wt32 = (const uint32_t*)Wt;
    const int arow = mw * 32 + (lane >> 2);
    const int brow = nw * 64 + (lane >> 2);
    const int koff = (lane & 3);

    for (int tile = blockIdx.x; tile < nTiles; tile += gridDim.x) {
        const int row0 = tile * 128;

        // Load 128x256 fp32 X slab -> fp16 smem (zero pad past N)
        for (int p = tid; p < 128 * 64; p += 512) {
            int r  = p >> 6;
            int c4 = p & 63;
            int gr = row0 + r;
            float4 v = make_float4(0.f, 0.f, 0.f, 0.f);
            if (gr < N) v = ((const float4*)x)[(size_t)gr * 64 + c4];
            __half2* dst = (__half2*)&As[r * WT_STRIDE + c4 * 4];
            dst[0] = __floats2half2_rn(v.x, v.y);
            dst[1] = __floats2half2_rn(v.z, v.w);
        }
        if (tid < 128) red[tid] = 0.f;
        __syncthreads();

        // GEMM: 128 x 256 x 256, warp tile 32x64 (2 m16 x 8 n8), k-step 16
        float c[2][8][4];
        #pragma unroll
        for (int t = 0; t < 2; t++)
            #pragma unroll
            for (int nt = 0; nt < 8; nt++)
                #pragma unroll
                for (int q = 0; q < 4; q++) c[t][nt][q] = 0.f;

        #pragma unroll 1
        for (int ks = 0; ks < 16; ks++) {
            const int kb = ks * 8 + koff;   // u32 index within padded row
            uint32_t a[2][4];
            #pragma unroll
            for (int t = 0; t < 2; t++) {
                int r = arow + t * 16;
                a[t][0] = As32[r * 132 + kb];
                a[t][1] = As32[(r + 8) * 132 + kb];
                a[t][2] = As32[r * 132 + kb + 4];
                a[t][3] = As32[(r + 8) * 132 + kb + 4];
            }
            #pragma unroll
            for (int nt = 0; nt < 8; nt++) {
                int n = brow + nt * 8;
                uint32_t bb0 = Wt32[n * 132 + kb];
                uint32_t bb1 = Wt32[n * 132 + kb + 4];
                #pragma unroll
                for (int t = 0; t < 2; t++) {
                    asm volatile(
                        "mma.sync.aligned.m16n8k16.row.col.f32.f16.f16.f32 "
                        "{%0,%1,%2,%3}, {%4,%5,%6,%7}, {%8,%9}, {%0,%1,%2,%3};\n"
                        : "+f"(c[t][nt][0]), "+f"(c[t][nt][1]),
                          "+f"(c[t][nt][2]), "+f"(c[t][nt][3])
                        : "r"(a[t][0]), "r"(a[t][1]), "r"(a[t][2]), "r"(a[t][3]),
                          "r"(bb0), "r"(bb1));
                }
            }
        }

        // Epilogue: s partial = sum_j tanh(h + b1[j]) * w2[j]
        #pragma unroll
        for (int t = 0; t < 2; t++) {
            float p0 = 0.f, p1 = 0.f;
            #pragma unroll
            for (int nt = 0; nt < 8; nt++) {
                int j0 = nw * 64 + nt * 8 + 2 * (lane & 3);
                float bb0 = b1s[j0], bb1 = b1s[j0 + 1];
                float ww0 = w2s[j0], ww1 = w2s[j0 + 1];
                p0 += tanh_fast(c[t][nt][0] + bb0) * ww0 + tanh_fast(c[t][nt][1] + bb1) * ww1;
                p1 += tanh_fast(c[t][nt][2] + bb0) * ww0 + tanh_fast(c[t][nt][3] + bb1) * ww1;
            }
            p0 += __shfl_xor_sync(0xffffffffu, p0, 1);
            p0 += __shfl_xor_sync(0xffffffffu, p0, 2);
            p1 += __shfl_xor_sync(0xffffffffu, p1, 1);
            p1 += __shfl_xor_sync(0xffffffffu, p1, 2);
            if ((lane & 3) == 0) {
                int r0 = mw * 32 + t * 16 + (lane >> 2);
                atomicAdd(&red[r0], p0);
                atomicAdd(&red[r0 + 8], p1);
            }
        }
        __syncthreads();
        if (tid < 128) {
            int gr = row0 + tid;
            if (gr < N) s_out[gr] = red[tid] + b2;
        }
        __syncthreads();
    }
}

// ---------------- segment softmax + pooling ----------------
// batch may be int32 (JAX x64-disabled demotes int64->int32) or genuine int64.
// Probe: for an int64 buffer holding values < 2^31, int32 word at index N-1 is
// the upper half of element (N-1)/2 == 0. For an int32 buffer it is the last
// (largest) batch id, nonzero in practice. Deterministic, uniform per block.
__device__ __forceinline__ int batch_at(const int* b32, int i, bool is64) {
    return is64 ? b32[2 * i] : b32[i];   // little-endian lower word
}

__global__ __launch_bounds__(256)
void pool_kernel(const float* __restrict__ x,
                 const int* __restrict__ batch32,
                 const float* __restrict__ s,
                 float* __restrict__ pooled,
                 int N)
{
    __shared__ float rbuf[256];
    __shared__ float alphas[256];

    const int b   = blockIdx.x;
    const int tid = threadIdx.x;
    const bool is64 = (batch32[N - 1] == 0);

    // binary search segment bounds in sorted batch
    int lo = 0, hi = N;
    while (lo < hi) { int mid = (lo + hi) >> 1; if (batch_at(batch32, mid, is64) < b) lo = mid + 1; else hi = mid; }
    const int start = lo;
    hi = N;
    while (lo < hi) { int mid = (lo + hi) >> 1; if (batch_at(batch32, mid, is64) < b + 1) lo = mid + 1; else hi = mid; }
    const int end = lo;

    // phase 1: segment max
    float m = -INFINITY;
    for (int i = start + tid; i < end; i += 256) m = fmaxf(m, s[i]);
    rbuf[tid] = m; __syncthreads();
    for (int off = 128; off > 0; off >>= 1) {
        if (tid < off) rbuf[tid] = fmaxf(rbuf[tid], rbuf[tid + off]);
        __syncthreads();
    }
    const float smax = rbuf[0];
    __syncthreads();

    // phase 2: sum of exp
    float sum = 0.f;
    for (int i = start + tid; i < end; i += 256) sum += __expf(s[i] - smax);
    rbuf[tid] = sum; __syncthreads();
    for (int off = 128; off > 0; off >>= 1) {
        if (tid < off) rbuf[tid] += rbuf[tid + off];
        __syncthreads();
    }
    const float inv = 1.0f / rbuf[0];
    __syncthreads();

    // phase 3: weighted accumulation, 256-row chunks
    float a0 = 0.f, a1 = 0.f, a2 = 0.f, a3 = 0.f;
    for (int c0 = start; c0 < end; c0 += 256) {
        const int cnt = min(256, end - c0);
        if (tid < cnt) alphas[tid] = __expf(s[c0 + tid] - smax) * inv;
        __syncthreads();
        int r = 0;
        for (; r + 4 <= cnt; r += 4) {
            float x0 = x[(size_t)(c0 + r + 0) * DDIM + tid];
            float x1 = x[(size_t)(c0 + r + 1) * DDIM + tid];
            float x2 = x[(size_t)(c0 + r + 2) * DDIM + tid];
            float x3 = x[(size_t)(c0 + r + 3) * DDIM + tid];
            a0 += alphas[r + 0] * x0;
            a1 += alphas[r + 1] * x1;
            a2 += alphas[r + 2] * x2;
            a3 += alphas[r + 3] * x3;
        }
        for (; r < cnt; r++)
            a0 += alphas[r] * x[(size_t)(c0 + r) * DDIM + tid];
        __syncthreads();
    }
    pooled[b * DDIM + tid] = (a0 + a1) + (a2 + a3);
}

// ---------------- output GEMM: out = pooled @ Wp + bp ----------------
__global__ __launch_bounds__(256)
void out_kernel(const float* __restrict__ pooled,
                const float* __restrict__ Wp,
                const float* __restrict__ bp,
                float* __restrict__ out)
{
    __shared__ float ps[16][DDIM];
    const int b0  = blockIdx.x * 16;
    const int tid = threadIdx.x;

    for (int p = tid; p < 16 * DDIM; p += 256)
        ps[p >> 8][p & 255] = pooled[b0 * DDIM + p];
    __syncthreads();

    float acc[16];
    #pragma unroll
    for (int r = 0; r < 16; r++) acc[r] = 0.f;

    for (int k = 0; k < DDIM; k++) {
        float w = Wp[k * DDIM + tid];
        #pragma unroll
        for (int r = 0; r < 16; r++) acc[r] += ps[r][k] * w;
    }
    const float bias = bp[tid];
    #pragma unroll
    for (int r = 0; r < 16; r++) out[(b0 + r) * DDIM + tid] = acc[r] + bias;
}

// ---------------- launch ----------------
extern "C" void kernel_launch(void* const* d_in, const int* in_sizes, int n_in,
                              void* d_out, int out_size)
{
    const float* x     = (const float*)d_in[0];
    const int*   batch = (const int*)d_in[1];   // int32 or int64; probed on device
    const float* W1    = (const float*)d_in[2];
    const float* b1    = (const float*)d_in[3];
    const float* w2    = (const float*)d_in[4];
    const float* b2    = (const float*)d_in[5];
    const float* Wp    = (const float*)d_in[6];
    const float* bp    = (const float*)d_in[7];
    float*       out   = (float*)d_out;

    const int N  = in_sizes[0] / DDIM;   // 1,000,000
    const int Bn = out_size / DDIM;      // 4096

    float* d_s;      cudaGetSymbolAddress((void**)&d_s, g_s);
    float* d_pooled; cudaGetSymbolAddress((void**)&d_pooled, g_pooled);

    const int nTiles = (N + 127) / 128;
    cudaFuncSetAttribute(score_kernel, cudaFuncAttributeMaxDynamicSharedMemorySize, SMEM_BYTES);
    score_kernel<<<152, 512, SMEM_BYTES>>>(x, W1, b1, w2, b2, d_s, N, nTiles);
    pool_kernel<<<Bn, 256>>>(x, batch, d_s, d_pooled, N);
    out_kernel<<<Bn / 16, 256>>>(d_pooled, Wp, bp, out);
}